// round 9
// baseline (speedup 1.0000x reference)
#include <cuda_runtime.h>
#include <cuda_fp16.h>
#include <cstdint>

// ============================================================================
// GraphConvolution: out = (adj-premixed F) @ W^T + bias, fp16 MMA, fp32 accum.
// R9: warp-specialized. 512-thread CTA, MTILE=64:
//   warps 0-7  (consumers): pure ldmatrix+mma, warp tile 32x64 (2M x 4N)
//   warps 8-15 (producers): A LDG + adj premix + STS, B cp.async 3-stage ring
// Named-barrier FULL/EMPTY handshake, producer runs one chunk ahead.
// ============================================================================

#define KDIM    1024
#define NOUTD   256
#define MTILE   64
#define KC      64
#define NCHUNK  (KDIM / KC)          // 16
#define THREADS 512
#define ASLOT   (64 * 128)           // 8 KB per A slot (fp16, 128B rows)
#define BSTAGE  (256 * 128)          // 32 KB per B stage
#define SMEM_B0 (2 * ASLOT)          // 16384
#define SMEMB   (SMEM_B0 + 3 * BSTAGE)  // 114688 = 112 KB

__device__ __align__(16) __half WhalfG[NOUTD * KDIM];   // 512 KB scratch

// ---------------- helpers ----------------
__device__ __forceinline__ uint32_t smem_u32(const void* p) {
    uint32_t a;
    asm("{ .reg .u64 t; cvta.to.shared.u64 t, %1; cvt.u32.u64 %0, t; }" : "=r"(a) : "l"(p));
    return a;
}
__device__ __forceinline__ uint32_t swz(int row, int colbyte) {
    return (uint32_t)(row * 128 + (colbyte ^ ((row & 7) << 4)));
}
__device__ __forceinline__ void ldmatrix_x4(uint32_t& r0, uint32_t& r1,
                                            uint32_t& r2, uint32_t& r3, uint32_t addr) {
    asm volatile("ldmatrix.sync.aligned.m8n8.x4.shared.b16 {%0,%1,%2,%3}, [%4];"
                 : "=r"(r0), "=r"(r1), "=r"(r2), "=r"(r3) : "r"(addr));
}
__device__ __forceinline__ void mma16816(float* c, const uint32_t* a,
                                         uint32_t b0, uint32_t b1) {
    asm volatile("mma.sync.aligned.m16n8k16.row.col.f32.f16.f16.f32 "
                 "{%0,%1,%2,%3}, {%4,%5,%6,%7}, {%8,%9}, {%0,%1,%2,%3};"
                 : "+f"(c[0]), "+f"(c[1]), "+f"(c[2]), "+f"(c[3])
                 : "r"(a[0]), "r"(a[1]), "r"(a[2]), "r"(a[3]), "r"(b0), "r"(b1));
}
__device__ __forceinline__ uint32_t h2u(__half2 h) {
    return *reinterpret_cast<uint32_t*>(&h);
}
__device__ __forceinline__ void cp_async16(uint32_t dst, const void* src) {
    asm volatile("cp.async.cg.shared.global [%0], [%1], 16;" :: "r"(dst), "l"(src));
}
#define CP_COMMIT() asm volatile("cp.async.commit_group;" ::: "memory")
#define CP_WAIT1()  asm volatile("cp.async.wait_group 1;" ::: "memory")
// Named barriers: FULL parity ids 1,2 ; EMPTY parity ids 3,4. Count = 512.
#define BAR_SYNC(id)   asm volatile("bar.sync %0, 512;"   :: "r"(id) : "memory")
#define BAR_ARRIVE(id) asm volatile("bar.arrive %0, 512;" :: "r"(id) : "memory")

// ---------------- kernel 1: W fp32 -> fp16 ----------------
__global__ void convW_kernel(const float* __restrict__ W) {
    int i = blockIdx.x * blockDim.x + threadIdx.x;        // 65536 threads, 4 f each
    float4 v = reinterpret_cast<const float4*>(W)[i];
    uint2 u = make_uint2(h2u(__floats2half2_rn(v.x, v.y)),
                         h2u(__floats2half2_rn(v.z, v.w)));
    reinterpret_cast<uint2*>(WhalfG)[i] = u;
}

// ---------------- kernel 2: warp-specialized premix + GEMM ----------------
__global__ void __launch_bounds__(THREADS, 1) gconv_gemm_kernel(
    const float* __restrict__ adj,   // [4,4]
    const float* __restrict__ F,     // [32768,1024]
    const float* __restrict__ bias,  // [256]
    float* __restrict__ out)         // [32768,256]
{
    extern __shared__ char smem[];
    const uint32_t sbase = smem_u32(smem);
    const int tid  = threadIdx.x;
    const int warp = tid >> 5;
    const int lane = tid & 31;
    const size_t tile_row = (size_t)blockIdx.x * MTILE;

    if (warp < 8) {
        // ================= CONSUMERS: pure ldmatrix + mma =================
        const int wm = warp & 1;     // 2 warps along M (32 rows)
        const int wn = warp >> 1;    // 4 warps along N (64 cols)

        float c[2][8][4];
#pragma unroll
        for (int i = 0; i < 2; i++)
#pragma unroll
            for (int j = 0; j < 8; j++)
#pragma unroll
                for (int k = 0; k < 4; k++) c[i][j][k] = 0.f;

        // XOR-hoisted ldmatrix offsets: addr(ks) = (base + off) ^ (ks<<5)
        const uint32_t aoff0 = swz(wm * 32 +  0 + (lane & 15), ((lane >> 4) & 1) * 16);
        const uint32_t aoff1 = swz(wm * 32 + 16 + (lane & 15), ((lane >> 4) & 1) * 16);
        const int brow = (lane & 7) + ((lane >> 4) & 1) * 8;
        const uint32_t bsel = ((lane >> 3) & 1) * 16;
        const uint32_t boff0 = swz(wn * 64 +  0 + brow, bsel);
        const uint32_t boff1 = swz(wn * 64 + 16 + brow, bsel);
        const uint32_t boff2 = swz(wn * 64 + 32 + brow, bsel);
        const uint32_t boff3 = swz(wn * 64 + 48 + brow, bsel);

        for (int ch = 0; ch < NCHUNK; ch++) {
            BAR_SYNC(1 + (ch & 1));                    // FULL(ch)
            const uint32_t sa = sbase + (ch & 1) * ASLOT;
            const uint32_t sb = sbase + SMEM_B0 + (ch % 3) * BSTAGE;
#pragma unroll
            for (int ks = 0; ks < 4; ks++) {
                const uint32_t kx = (uint32_t)(ks << 5);
                uint32_t a[2][4], b[4][4];
                ldmatrix_x4(a[0][0], a[0][1], a[0][2], a[0][3], (sa + aoff0) ^ kx);
                ldmatrix_x4(a[1][0], a[1][1], a[1][2], a[1][3], (sa + aoff1) ^ kx);
                ldmatrix_x4(b[0][0], b[0][1], b[0][2], b[0][3], (sb + boff0) ^ kx);
                ldmatrix_x4(b[1][0], b[1][1], b[1][2], b[1][3], (sb + boff1) ^ kx);
                ldmatrix_x4(b[2][0], b[2][1], b[2][2], b[2][3], (sb + boff2) ^ kx);
                ldmatrix_x4(b[3][0], b[3][1], b[3][2], b[3][3], (sb + boff3) ^ kx);
#pragma unroll
                for (int mf = 0; mf < 2; mf++)
#pragma unroll
                    for (int nf = 0; nf < 8; nf++)
                        mma16816(c[mf][nf], a[mf],
                                 b[nf >> 1][(nf & 1) * 2], b[nf >> 1][(nf & 1) * 2 + 1]);
            }
            if (ch + 1 < NCHUNK) BAR_ARRIVE(3 + (ch & 1));   // EMPTY(ch)
        }

        // ---- epilogue: + bias, store fp32 ----
        float2 bb[8];
#pragma unroll
        for (int nf = 0; nf < 8; nf++)
            bb[nf] = *reinterpret_cast<const float2*>(bias + wn * 64 + nf * 8 + (lane & 3) * 2);

#pragma unroll
        for (int mf = 0; mf < 2; mf++) {
#pragma unroll
            for (int nf = 0; nf < 8; nf++) {
                const size_t m = tile_row + wm * 32 + mf * 16 + (lane >> 2);
                const int n = wn * 64 + nf * 8 + (lane & 3) * 2;
                float2 o0 = make_float2(c[mf][nf][0] + bb[nf].x, c[mf][nf][1] + bb[nf].y);
                float2 o1 = make_float2(c[mf][nf][2] + bb[nf].x, c[mf][nf][3] + bb[nf].y);
                *reinterpret_cast<float2*>(out + m * NOUTD + n) = o0;
                *reinterpret_cast<float2*>(out + (m + 8) * NOUTD + n) = o1;
            }
        }
    } else {
        // ================= PRODUCERS: A premix + B cp.async =================
        const int ptid = tid - 256;          // 0..255
        const int quad = ptid >> 4;          // 0..15 -> rows 4*quad..4*quad+3
        const int cg   = ptid & 15;          // 0..15 -> cols cg*4..cg*4+3

        // adj in registers (producers only)
        const float4 A0 = __ldg((const float4*)(adj + 0));
        const float4 A1 = __ldg((const float4*)(adj + 4));
        const float4 A2 = __ldg((const float4*)(adj + 8));
        const float4 A3 = __ldg((const float4*)(adj + 12));

        float4 ra[4];

        auto loadA = [&](int ch) {
            const float* ap = F + (tile_row + 4 * quad) * (size_t)KDIM + ch * KC + cg * 4;
#pragma unroll
            for (int m = 0; m < 4; m++)
                ra[m] = *reinterpret_cast<const float4*>(ap + (size_t)m * KDIM);
        };

        auto storeA = [&](int slot) {
            char* sa = smem + slot * ASLOT;
#pragma unroll
            for (int n = 0; n < 4; n++) {
                const float4 an = (n == 0) ? A0 : (n == 1) ? A1 : (n == 2) ? A2 : A3;
                float ox = an.x * ra[0].x + an.y * ra[1].x + an.z * ra[2].x + an.w * ra[3].x;
                float oy = an.x * ra[0].y + an.y * ra[1].y + an.z * ra[2].y + an.w * ra[3].y;
                float oz = an.x * ra[0].z + an.y * ra[1].z + an.z * ra[2].z + an.w * ra[3].z;
                float ow = an.x * ra[0].w + an.y * ra[1].w + an.z * ra[2].w + an.w * ra[3].w;
                uint2 u = make_uint2(h2u(__floats2half2_rn(ox, oy)),
                                     h2u(__floats2half2_rn(oz, ow)));
                *reinterpret_cast<uint2*>(sa + swz(4 * quad + n, cg * 8)) = u;
            }
        };

        auto cpasyncB = [&](int ch, int stage) {
            const uint32_t bs = sbase + SMEM_B0 + stage * BSTAGE;
#pragma unroll
            for (int i = 0; i < 8; i++) {
                const int u = ptid + i * 256;        // 0..2047
                const int row = u >> 3;              // 0..255
                const int cb  = (u & 7) * 16;        // 0..112
                const char* src = reinterpret_cast<const char*>(WhalfG)
                                  + (size_t)row * 2048 + ch * 128 + cb;
                cp_async16(bs + swz(row, cb), src);
            }
        };

        // ---- prologue: ready chunk 0, signal FULL(0) ----
        cpasyncB(0, 0); CP_COMMIT();
        cpasyncB(1, 1); CP_COMMIT();
        loadA(0); storeA(0);
        loadA(1);
        CP_WAIT1();                      // B(0) landed (B(1) in flight)
        __threadfence_block();           // STS + cp.async data visible CTA-wide
        BAR_ARRIVE(1);                   // FULL(0)

        // ---- producer loop: iter ch readies chunk ch+1 ----
        for (int ch = 0; ch < NCHUNK - 1; ch++) {
            if (ch + 2 < NCHUNK) cpasyncB(ch + 2, (ch + 2) % 3);
            CP_COMMIT();                 // unconditional -> constant wait depth
            storeA((ch + 1) & 1);
            if (ch + 2 < NCHUNK) loadA(ch + 2);
            CP_WAIT1();                  // B(ch+1) landed
            __threadfence_block();
            BAR_ARRIVE(1 + ((ch + 1) & 1));   // FULL(ch+1)
            BAR_SYNC(3 + (ch & 1));           // EMPTY(ch): consumers done with ch
        }
    }
}

// ============================================================================
extern "C" void kernel_launch(void* const* d_in, const int* in_sizes, int n_in,
                              void* d_out, int out_size) {
    (void)in_sizes; (void)n_in; (void)out_size;
    const float* adj  = (const float*)d_in[0];   // [4,4]
    const float* F    = (const float*)d_in[1];   // [8192,4,1024]
    const float* W    = (const float*)d_in[2];   // [256,1024]
    const float* bias = (const float*)d_in[3];   // [256]
    float* out = (float*)d_out;                  // [8192,4,256]

    convW_kernel<<<256, 256>>>(W);

    cudaFuncSetAttribute(gconv_gemm_kernel,
                         cudaFuncAttributeMaxDynamicSharedMemorySize, SMEMB);
    gconv_gemm_kernel<<<32768 / MTILE, THREADS, SMEMB>>>(adj, F, bias, out);
}

// round 11
// speedup vs baseline: 1.5005x; 1.5005x over previous
#include <cuda_runtime.h>
#include <cuda_fp16.h>
#include <cstdint>

// ============================================================================
// GraphConvolution: out = (adj-premixed F) @ W^T + bias, fp16 MMA, fp32 accum.
// R10 = R7 (best: 71.7us) + restructured ks inner loop: B fragments loaded in
// x4 groups interleaved with their MMA consumers (live B regs 16->8), giving
// ptxas slack under the 128-reg cap to software-pipeline ldmatrix vs HMMA.
// 256-thread CTA (M64 x N256), 2 CTAs/SM, cp.async 3-stage B ring,
// zero-shfl quad-local premix, MMA-first order. Warp tile 32x64 (2Mx4N).
// ============================================================================

#define KDIM    1024
#define NOUTD   256
#define MTILE   64
#define KC      64
#define NCHUNK  (KDIM / KC)          // 16
#define THREADS 256
#define ASLOT   (64 * 128)           // 8 KB per A slot (fp16, 128B rows)
#define BSTAGE  (256 * 128)          // 32 KB per B stage
#define SMEM_B0 (2 * ASLOT)          // 16384
#define SMEMB   (SMEM_B0 + 3 * BSTAGE)  // 114688 = 112 KB

__device__ __align__(16) __half WhalfG[NOUTD * KDIM];   // 512 KB scratch

// ---------------- helpers ----------------
__device__ __forceinline__ uint32_t smem_u32(const void* p) {
    uint32_t a;
    asm("{ .reg .u64 t; cvta.to.shared.u64 t, %1; cvt.u32.u64 %0, t; }" : "=r"(a) : "l"(p));
    return a;
}
__device__ __forceinline__ uint32_t swz(int row, int colbyte) {
    return (uint32_t)(row * 128 + (colbyte ^ ((row & 7) << 4)));
}
__device__ __forceinline__ void ldmatrix_x4(uint32_t& r0, uint32_t& r1,
                                            uint32_t& r2, uint32_t& r3, uint32_t addr) {
    asm volatile("ldmatrix.sync.aligned.m8n8.x4.shared.b16 {%0,%1,%2,%3}, [%4];"
                 : "=r"(r0), "=r"(r1), "=r"(r2), "=r"(r3) : "r"(addr));
}
__device__ __forceinline__ void mma16816(float* c, const uint32_t* a,
                                         uint32_t b0, uint32_t b1) {
    asm volatile("mma.sync.aligned.m16n8k16.row.col.f32.f16.f16.f32 "
                 "{%0,%1,%2,%3}, {%4,%5,%6,%7}, {%8,%9}, {%0,%1,%2,%3};"
                 : "+f"(c[0]), "+f"(c[1]), "+f"(c[2]), "+f"(c[3])
                 : "r"(a[0]), "r"(a[1]), "r"(a[2]), "r"(a[3]), "r"(b0), "r"(b1));
}
__device__ __forceinline__ uint32_t h2u(__half2 h) {
    return *reinterpret_cast<uint32_t*>(&h);
}
__device__ __forceinline__ void cp_async16(uint32_t dst, const void* src) {
    asm volatile("cp.async.cg.shared.global [%0], [%1], 16;" :: "r"(dst), "l"(src));
}
#define CP_COMMIT() asm volatile("cp.async.commit_group;" ::: "memory")
#define CP_WAIT1()  asm volatile("cp.async.wait_group 1;" ::: "memory")

// ---------------- kernel 1: W fp32 -> fp16 ----------------
__global__ void convW_kernel(const float* __restrict__ W) {
    int i = blockIdx.x * blockDim.x + threadIdx.x;        // 65536 threads, 4 f each
    float4 v = reinterpret_cast<const float4*>(W)[i];
    uint2 u = make_uint2(h2u(__floats2half2_rn(v.x, v.y)),
                         h2u(__floats2half2_rn(v.z, v.w)));
    reinterpret_cast<uint2*>(WhalfG)[i] = u;
}

// ---------------- kernel 2: fused premix + GEMM ----------------
__global__ void __launch_bounds__(THREADS, 2) gconv_gemm_kernel(
    const float* __restrict__ adj,   // [4,4]
    const float* __restrict__ F,     // [32768,1024]
    const float* __restrict__ bias,  // [256]
    float* __restrict__ out)         // [32768,256]
{
    extern __shared__ char smem[];
    const uint32_t sbase = smem_u32(smem);
    const int tid  = threadIdx.x;
    const int warp = tid >> 5;
    const int lane = tid & 31;
    const int wm   = warp & 1;       // 2 warps along M
    const int wn   = warp >> 1;      // 4 warps along N
    const size_t tile_row = (size_t)blockIdx.x * MTILE;

    // Full adj matrix per thread (local zero-shfl premix)
    const float4 A0 = __ldg((const float4*)(adj + 0));
    const float4 A1 = __ldg((const float4*)(adj + 4));
    const float4 A2 = __ldg((const float4*)(adj + 8));
    const float4 A3 = __ldg((const float4*)(adj + 12));

    float c[2][8][4];
#pragma unroll
    for (int i = 0; i < 2; i++)
#pragma unroll
        for (int j = 0; j < 8; j++)
#pragma unroll
            for (int k = 0; k < 4; k++) c[i][j][k] = 0.f;

    // A staging: 4 source rows x 4 cols (quad-local premix)
    const int quad = tid >> 4;       // 0..15  -> rows 4*quad .. 4*quad+3
    const int cg   = tid & 15;       // 0..15  -> cols cg*4 .. cg*4+3
    float4 ra[4];

    auto loadA = [&](int ch) {
        const float* ap = F + (tile_row + 4 * quad) * (size_t)KDIM + ch * KC + cg * 4;
#pragma unroll
        for (int m = 0; m < 4; m++)
            ra[m] = *reinterpret_cast<const float4*>(ap + (size_t)m * KDIM);
    };

    auto storeA = [&](int slot) {
        char* sa = smem + slot * ASLOT;
#pragma unroll
        for (int n = 0; n < 4; n++) {
            const float4 an = (n == 0) ? A0 : (n == 1) ? A1 : (n == 2) ? A2 : A3;
            float ox = an.x * ra[0].x + an.y * ra[1].x + an.z * ra[2].x + an.w * ra[3].x;
            float oy = an.x * ra[0].y + an.y * ra[1].y + an.z * ra[2].y + an.w * ra[3].y;
            float oz = an.x * ra[0].z + an.y * ra[1].z + an.z * ra[2].z + an.w * ra[3].z;
            float ow = an.x * ra[0].w + an.y * ra[1].w + an.z * ra[2].w + an.w * ra[3].w;
            uint2 u = make_uint2(h2u(__floats2half2_rn(ox, oy)),
                                 h2u(__floats2half2_rn(oz, ow)));
            *reinterpret_cast<uint2*>(sa + swz(4 * quad + n, cg * 8)) = u;
        }
    };

    // ---- B: cp.async fp16 W chunk into smem stage (128B per thread) ----
    auto cpasyncB = [&](int ch, int stage) {
        const uint32_t bs = sbase + SMEM_B0 + stage * BSTAGE;
#pragma unroll
        for (int i = 0; i < 8; i++) {
            const int u = tid + i * THREADS;     // 0..2047
            const int row = u >> 3;              // 0..255
            const int cb  = (u & 7) * 16;        // 0..112
            const char* src = reinterpret_cast<const char*>(WhalfG)
                              + (size_t)row * 2048 + ch * 128 + cb;
            cp_async16(bs + swz(row, cb), src);
        }
    };

    // XOR-hoisted ldmatrix offsets: addr(ks) = (base + off) ^ (ks<<5)
    const uint32_t aoff0 = swz(wm * 32 +  0 + (lane & 15), ((lane >> 4) & 1) * 16);
    const uint32_t aoff1 = swz(wm * 32 + 16 + (lane & 15), ((lane >> 4) & 1) * 16);
    const int brow = (lane & 7) + ((lane >> 4) & 1) * 8;
    const uint32_t bsel = ((lane >> 3) & 1) * 16;
    const uint32_t boff0 = swz(wn * 64 +  0 + brow, bsel);
    const uint32_t boff1 = swz(wn * 64 + 16 + brow, bsel);
    const uint32_t boff2 = swz(wn * 64 + 32 + brow, bsel);
    const uint32_t boff3 = swz(wn * 64 + 48 + brow, bsel);

    // ---- prologue ----
    cpasyncB(0, 0); CP_COMMIT();
    cpasyncB(1, 1); CP_COMMIT();
    loadA(0); storeA(0);
    loadA(1);

    // ---- main loop (MMA-first; premix/loads in the tensor shadow) ----
    for (int ch = 0; ch < NCHUNK; ch++) {
        CP_WAIT1();                 // B(ch) arrived (B(ch+1) may be in flight)
        __syncthreads();            // A(ch) visible; MMA(ch-1) done everywhere

        if (ch + 2 < NCHUNK) cpasyncB(ch + 2, (ch + 2) % 3);
        CP_COMMIT();                // commit every iter -> constant wait depth

        const uint32_t sa = sbase + (ch & 1) * ASLOT;
        const uint32_t sb = sbase + SMEM_B0 + (ch % 3) * BSTAGE;
#pragma unroll
        for (int ks = 0; ks < 4; ks++) {
            const uint32_t kx = (uint32_t)(ks << 5);
            uint32_t a[2][4];
            uint32_t b0[4], b1[4], b2[4], b3[4];
            // B group 0 first (earliest consumer), then A, then interleave:
            // each ldmatrix has a full 4-MMA group in front of its consumer.
            ldmatrix_x4(b0[0], b0[1], b0[2], b0[3], (sb + boff0) ^ kx);
            ldmatrix_x4(a[0][0], a[0][1], a[0][2], a[0][3], (sa + aoff0) ^ kx);
            ldmatrix_x4(a[1][0], a[1][1], a[1][2], a[1][3], (sa + aoff1) ^ kx);
            ldmatrix_x4(b1[0], b1[1], b1[2], b1[3], (sb + boff1) ^ kx);
            mma16816(c[0][0], a[0], b0[0], b0[1]);
            mma16816(c[0][1], a[0], b0[2], b0[3]);
            mma16816(c[1][0], a[1], b0[0], b0[1]);
            mma16816(c[1][1], a[1], b0[2], b0[3]);
            ldmatrix_x4(b2[0], b2[1], b2[2], b2[3], (sb + boff2) ^ kx);
            mma16816(c[0][2], a[0], b1[0], b1[1]);
            mma16816(c[0][3], a[0], b1[2], b1[3]);
            mma16816(c[1][2], a[1], b1[0], b1[1]);
            mma16816(c[1][3], a[1], b1[2], b1[3]);
            ldmatrix_x4(b3[0], b3[1], b3[2], b3[3], (sb + boff3) ^ kx);
            mma16816(c[0][4], a[0], b2[0], b2[1]);
            mma16816(c[0][5], a[0], b2[2], b2[3]);
            mma16816(c[1][4], a[1], b2[0], b2[1]);
            mma16816(c[1][5], a[1], b2[2], b2[3]);
            mma16816(c[0][6], a[0], b3[0], b3[1]);
            mma16816(c[0][7], a[0], b3[2], b3[3]);
            mma16816(c[1][6], a[1], b3[0], b3[1]);
            mma16816(c[1][7], a[1], b3[2], b3[3]);
        }

        // premix + next-next A load AFTER the MMA block (tensor already running)
        if (ch + 1 < NCHUNK) storeA((ch + 1) & 1);  // slot free: MMA(ch-1) retired
        if (ch + 2 < NCHUNK) loadA(ch + 2);         // consumed after MMA(ch+1)
    }

    // ---- epilogue: + bias, store fp32 ----
    float2 bb[8];
#pragma unroll
    for (int nf = 0; nf < 8; nf++)
        bb[nf] = *reinterpret_cast<const float2*>(bias + wn * 64 + nf * 8 + (lane & 3) * 2);

#pragma unroll
    for (int mf = 0; mf < 2; mf++) {
#pragma unroll
        for (int nf = 0; nf < 8; nf++) {
            const size_t m = tile_row + wm * 32 + mf * 16 + (lane >> 2);
            const int n = wn * 64 + nf * 8 + (lane & 3) * 2;
            float2 o0 = make_float2(c[mf][nf][0] + bb[nf].x, c[mf][nf][1] + bb[nf].y);
            float2 o1 = make_float2(c[mf][nf][2] + bb[nf].x, c[mf][nf][3] + bb[nf].y);
            *reinterpret_cast<float2*>(out + m * NOUTD + n) = o0;
            *reinterpret_cast<float2*>(out + (m + 8) * NOUTD + n) = o1;
        }
    }
}

// ============================================================================
extern "C" void kernel_launch(void* const* d_in, const int* in_sizes, int n_in,
                              void* d_out, int out_size) {
    (void)in_sizes; (void)n_in; (void)out_size;
    const float* adj  = (const float*)d_in[0];   // [4,4]
    const float* F    = (const float*)d_in[1];   // [8192,4,1024]
    const float* W    = (const float*)d_in[2];   // [256,1024]
    const float* bias = (const float*)d_in[3];   // [256]
    float* out = (float*)d_out;                  // [8192,4,256]

    convW_kernel<<<256, 256>>>(W);

    cudaFuncSetAttribute(gconv_gemm_kernel,
                         cudaFuncAttributeMaxDynamicSharedMemorySize, SMEMB);
    gconv_gemm_kernel<<<32768 / MTILE, THREADS, SMEMB>>>(adj, F, bias, out);
}